// round 3
// baseline (speedup 1.0000x reference)
#include <cuda_runtime.h>
#include <cuda_bf16.h>

#define BB   32
#define CC   512
#define HH   56
#define WW   56
#define HW   3136            // 56*56
#define BC   (BB*CC)         // 16384
#define BHW  (BB*HW)         // 100352
#define CSPLIT 4
#define CGRP  (CC/CSPLIT)    // 128
#define CHUNK 1024           // hw positions per k2 block (256 thr * float4)

__device__ float g_keep[BC];
__device__ float g_xmax[BC];
__device__ float g_psum[BC];
__device__ float g_thres[BC];
__device__ float g_bb[BHW];
__device__ float g_pmax[CSPLIT * BHW];   // stage-2 channel-group partial max
__device__ float g_pcsm[CSPLIT * BHW];   // stage-2 channel-group partial sum

// ---------------------------------------------------------------------------
// K1: per-(b,c) spatial sum/max of relu(x) -> keep mask
// ---------------------------------------------------------------------------
__global__ void k1_keep(const float* __restrict__ x) {
    int bc = blockIdx.x;
    const float4* row = (const float4*)(x + (size_t)bc * HW);
    float s = 0.f, m = 0.f;
    for (int i = threadIdx.x; i < HW / 4; i += blockDim.x) {
        float4 v = row[i];
        float a = fmaxf(v.x, 0.f), b = fmaxf(v.y, 0.f);
        float c = fmaxf(v.z, 0.f), d = fmaxf(v.w, 0.f);
        s += (a + b) + (c + d);
        m = fmaxf(m, fmaxf(fmaxf(a, b), fmaxf(c, d)));
    }
    __shared__ float ss[8], sm[8];
    #pragma unroll
    for (int o = 16; o; o >>= 1) {
        s += __shfl_down_sync(0xFFFFFFFFu, s, o);
        m  = fmaxf(m, __shfl_down_sync(0xFFFFFFFFu, m, o));
    }
    int wid = threadIdx.x >> 5, lid = threadIdx.x & 31;
    if (lid == 0) { ss[wid] = s; sm[wid] = m; }
    __syncthreads();
    if (threadIdx.x == 0) {
        float S = 0.f, M = 0.f;
        #pragma unroll
        for (int i = 0; i < 8; i++) { S += ss[i]; M = fmaxf(M, sm[i]); }
        g_keep[bc] = ((M - S * (1.0f / HW)) < 0.5f) ? 0.f : 1.f;
    }
}

// ---------------------------------------------------------------------------
// K2: channel-group partial max/sum of masked relu(x) at each (b,hw).
// Block: (hw-chunk, c-group, b). Thread owns 4 contiguous hw positions,
// loops over 128 channels — every load is a coalesced float4. Register accum.
// ---------------------------------------------------------------------------
__global__ void __launch_bounds__(256) k2_cred(const float* __restrict__ x) {
    __shared__ float skeep[CGRP];
    int b  = blockIdx.z;
    int cs = blockIdx.y;
    int c0 = cs * CGRP;
    if (threadIdx.x < CGRP) skeep[threadIdx.x] = g_keep[b * CC + c0 + threadIdx.x];
    __syncthreads();

    int pos = blockIdx.x * CHUNK + threadIdx.x * 4;
    if (pos >= HW) return;

    const float* xb = x + ((size_t)b * CC + c0) * HW + pos;
    float4 mx = make_float4(0.f, 0.f, 0.f, 0.f);
    float4 sm = make_float4(0.f, 0.f, 0.f, 0.f);
    #pragma unroll 4
    for (int c = 0; c < CGRP; c++) {
        float4 v = *(const float4*)(xb + (size_t)c * HW);
        float k = skeep[c];
        v.x = k * fmaxf(v.x, 0.f); v.y = k * fmaxf(v.y, 0.f);
        v.z = k * fmaxf(v.z, 0.f); v.w = k * fmaxf(v.w, 0.f);
        mx.x = fmaxf(mx.x, v.x); mx.y = fmaxf(mx.y, v.y);
        mx.z = fmaxf(mx.z, v.z); mx.w = fmaxf(mx.w, v.w);
        sm.x += v.x; sm.y += v.y; sm.z += v.z; sm.w += v.w;
    }
    size_t o = (size_t)cs * BHW + (size_t)b * HW + pos;
    *(float4*)(g_pmax + o) = mx;
    *(float4*)(g_pcsm + o) = sm;
}

// ---------------------------------------------------------------------------
// K2b: merge 4 channel-group partials -> bb per (b,hw)
// ---------------------------------------------------------------------------
__global__ void k2b_bb() {
    int i = (blockIdx.x * blockDim.x + threadIdx.x) * 4;
    if (i >= BHW) return;
    float4 mx = *(const float4*)(g_pmax + i);
    float4 sm = *(const float4*)(g_pcsm + i);
    #pragma unroll
    for (int cs = 1; cs < CSPLIT; cs++) {
        float4 m2 = *(const float4*)(g_pmax + (size_t)cs * BHW + i);
        float4 s2 = *(const float4*)(g_pcsm + (size_t)cs * BHW + i);
        mx.x = fmaxf(mx.x, m2.x); mx.y = fmaxf(mx.y, m2.y);
        mx.z = fmaxf(mx.z, m2.z); mx.w = fmaxf(mx.w, m2.w);
        sm.x += s2.x; sm.y += s2.y; sm.z += s2.z; sm.w += s2.w;
    }
    float4 bb;
    bb.x = 1.f - expf(-(mx.x - sm.x * (1.0f / CC)));
    bb.y = 1.f - expf(-(mx.y - sm.y * (1.0f / CC)));
    bb.z = 1.f - expf(-(mx.z - sm.z * (1.0f / CC)));
    bb.w = 1.f - expf(-(mx.w - sm.w * (1.0f / CC)));
    *(float4*)(g_bb + i) = bb;
}

// ---------------------------------------------------------------------------
// K3: per-(b,c) spatial max/sum of x2 = bb * keep * relu(x).
// bb rows (12.5 KB per b) are L2-resident across the 512 channels of a b.
// No atomics — each (b,c) fully reduced by one block.
// ---------------------------------------------------------------------------
__global__ void k3_stats(const float* __restrict__ x) {
    int bc = blockIdx.x, b = bc >> 9;
    float keep = g_keep[bc];
    const float4* row = (const float4*)(x + (size_t)bc * HW);
    const float4* bbr = (const float4*)(g_bb + (size_t)b * HW);
    float s = 0.f, m = 0.f;
    for (int i = threadIdx.x; i < HW / 4; i += blockDim.x) {
        float4 v = row[i];
        float4 g = bbr[i];
        float a = g.x * (keep * fmaxf(v.x, 0.f));
        float bq = g.y * (keep * fmaxf(v.y, 0.f));
        float c = g.z * (keep * fmaxf(v.z, 0.f));
        float d = g.w * (keep * fmaxf(v.w, 0.f));
        s += (a + bq) + (c + d);
        m = fmaxf(m, fmaxf(fmaxf(a, bq), fmaxf(c, d)));
    }
    __shared__ float ss[8], sm[8];
    #pragma unroll
    for (int o = 16; o; o >>= 1) {
        s += __shfl_down_sync(0xFFFFFFFFu, s, o);
        m  = fmaxf(m, __shfl_down_sync(0xFFFFFFFFu, m, o));
    }
    int wid = threadIdx.x >> 5, lid = threadIdx.x & 31;
    if (lid == 0) { ss[wid] = s; sm[wid] = m; }
    __syncthreads();
    if (threadIdx.x == 0) {
        float S = 0.f, M = 0.f;
        #pragma unroll
        for (int i = 0; i < 8; i++) { S += ss[i]; M = fmaxf(M, sm[i]); }
        g_xmax[bc] = M;
        g_psum[bc] = S;
    }
}

// ---------------------------------------------------------------------------
// K4: tiny FC gates -> thres per (b,c)
// ---------------------------------------------------------------------------
__global__ void k4_gates(const float* __restrict__ W1, const float* __restrict__ W3) {
    int b = blockIdx.x;
    __shared__ float pooled[CC];
    int c = threadIdx.x;
    pooled[c] = g_psum[b * CC + c] * (1.0f / HW);
    __syncthreads();
    float d1 = 0.f, d3 = 0.f;
    const float* w1r = W1 + (size_t)c * CC;
    const float* w3r = W3 + (size_t)c * CC;
    #pragma unroll 8
    for (int k = 0; k < CC; k++) {
        float p = pooled[k];
        d1 = fmaf(p, w1r[k], d1);
        d3 = fmaf(p, w3r[k], d3);
    }
    float c1 = 1.f / (1.f + expf(-d1));
    float r3 = fmaxf(d3, 0.f);
    float c3 = (r3 < 1.0f) ? 1.2f : r3;
    g_thres[b * CC + c] = c1 * c3 * g_xmax[b * CC + c];
}

// ---------------------------------------------------------------------------
// K5: final thresholding, recompute x2 from x + bb + keep (bb/keep/thres in L2)
// ---------------------------------------------------------------------------
__global__ void k5_final(const float* __restrict__ x, float* __restrict__ out) {
    unsigned v = blockIdx.x * blockDim.x + threadIdx.x;
    unsigned e = v * 4u;
    if (e >= (unsigned)BB * CC * HW) return;
    unsigned bc  = e / HW;
    unsigned pos = e % HW;
    unsigned b   = bc >> 9;
    float keep = g_keep[bc];
    float th   = g_thres[bc];
    float4 g = *(const float4*)(g_bb + b * HW + pos);
    float4 xv = *(const float4*)(x + e);
    float4 o;
    float t;
    t = g.x * (keep * fmaxf(xv.x, 0.f)); o.x = (t < th) ? 0.f : t;
    t = g.y * (keep * fmaxf(xv.y, 0.f)); o.y = (t < th) ? 0.f : t;
    t = g.z * (keep * fmaxf(xv.z, 0.f)); o.z = (t < th) ? 0.f : t;
    t = g.w * (keep * fmaxf(xv.w, 0.f)); o.w = (t < th) ? 0.f : t;
    *(float4*)(out + e) = o;
}

// ---------------------------------------------------------------------------
extern "C" void kernel_launch(void* const* d_in, const int* in_sizes, int n_in,
                              void* d_out, int out_size) {
    const float* x  = (const float*)d_in[0];
    const float* W1 = (const float*)d_in[1];
    const float* W3 = (const float*)d_in[2];
    float* out = (float*)d_out;

    k1_keep<<<BC, 256>>>(x);
    k2_cred<<<dim3((HW + CHUNK - 1) / CHUNK, CSPLIT, BB), 256>>>(x);   // (4,4,32)
    k2b_bb<<<(BHW / 4 + 255) / 256, 256>>>();
    k3_stats<<<BC, 256>>>(x);
    k4_gates<<<BB, CC>>>(W1, W3);
    unsigned nvec = (unsigned)BB * CC * HW / 4u;
    k5_final<<<(nvec + 255) / 256, 256>>>(x, out);
}

// round 5
// speedup vs baseline: 1.1181x; 1.1181x over previous
#include <cuda_runtime.h>
#include <cuda_bf16.h>

#define BB   32
#define CC   512
#define HH   56
#define WW   56
#define HW   3136            // 56*56
#define HW4  784             // HW/4 float4 per row = 24*32 + 16
#define BC   (BB*CC)         // 16384
#define BHW  (BB*HW)         // 100352
#define CSPLIT 4
#define CGRP  (CC/CSPLIT)    // 128
#define CHUNK 1024           // hw positions per k2 block (256 thr * float4)

__device__ float g_keep[BC];
__device__ float g_xmax[BC];
__device__ float g_psum[BC];
__device__ float g_thres[BC];
__device__ float g_bb[BHW];
__device__ float g_pmax[CSPLIT * BHW];
__device__ float g_pcsm[CSPLIT * BHW];

// ---------------------------------------------------------------------------
// K1: warp-per-(b,c)-row spatial sum/max of relu(x) -> keep mask.
// Barrier-free: 24 independent float4 loads per lane + 16-lane tail + shfl.
// ---------------------------------------------------------------------------
__global__ void __launch_bounds__(256) k1_keep(const float* __restrict__ x) {
    int gw   = (blockIdx.x * 256 + threadIdx.x) >> 5;   // warp id == bc
    int lane = threadIdx.x & 31;
    const float4* row = (const float4*)(x + (size_t)gw * HW);

    float s = 0.f, m = 0.f;
    #pragma unroll
    for (int i = 0; i < 24; i++) {
        float4 v = row[i * 32 + lane];
        float a = fmaxf(v.x, 0.f), b = fmaxf(v.y, 0.f);
        float c = fmaxf(v.z, 0.f), d = fmaxf(v.w, 0.f);
        s += (a + b) + (c + d);
        m = fmaxf(m, fmaxf(fmaxf(a, b), fmaxf(c, d)));
    }
    if (lane < 16) {
        float4 v = row[768 + lane];
        float a = fmaxf(v.x, 0.f), b = fmaxf(v.y, 0.f);
        float c = fmaxf(v.z, 0.f), d = fmaxf(v.w, 0.f);
        s += (a + b) + (c + d);
        m = fmaxf(m, fmaxf(fmaxf(a, b), fmaxf(c, d)));
    }
    #pragma unroll
    for (int o = 16; o; o >>= 1) {
        s += __shfl_down_sync(0xFFFFFFFFu, s, o);
        m  = fmaxf(m, __shfl_down_sync(0xFFFFFFFFu, m, o));
    }
    if (lane == 0)
        g_keep[gw] = ((m - s * (1.0f / HW)) < 0.5f) ? 0.f : 1.f;
}

// ---------------------------------------------------------------------------
// K2: channel-group partial max/sum of keep*relu(x) at each (b,hw).
// Thread owns 4 contiguous hw positions, loops over 128 channels (unroll 8).
// ---------------------------------------------------------------------------
__global__ void __launch_bounds__(256) k2_cred(const float* __restrict__ x) {
    __shared__ float skeep[CGRP];
    int b  = blockIdx.z;
    int cs = blockIdx.y;
    int c0 = cs * CGRP;
    if (threadIdx.x < CGRP) skeep[threadIdx.x] = g_keep[b * CC + c0 + threadIdx.x];
    __syncthreads();

    int pos = blockIdx.x * CHUNK + threadIdx.x * 4;
    if (pos >= HW) return;

    const float* xb = x + ((size_t)b * CC + c0) * HW + pos;
    float4 mx = make_float4(0.f, 0.f, 0.f, 0.f);
    float4 sm = make_float4(0.f, 0.f, 0.f, 0.f);
    #pragma unroll 8
    for (int c = 0; c < CGRP; c++) {
        float4 v = *(const float4*)(xb + (size_t)c * HW);
        float k = skeep[c];
        // keep >= 0  =>  keep*relu(x) == relu(keep*x)
        v.x = fmaxf(k * v.x, 0.f); v.y = fmaxf(k * v.y, 0.f);
        v.z = fmaxf(k * v.z, 0.f); v.w = fmaxf(k * v.w, 0.f);
        mx.x = fmaxf(mx.x, v.x); mx.y = fmaxf(mx.y, v.y);
        mx.z = fmaxf(mx.z, v.z); mx.w = fmaxf(mx.w, v.w);
        sm.x += v.x; sm.y += v.y; sm.z += v.z; sm.w += v.w;
    }
    size_t o = (size_t)cs * BHW + (size_t)b * HW + pos;
    *(float4*)(g_pmax + o) = mx;
    *(float4*)(g_pcsm + o) = sm;
}

// ---------------------------------------------------------------------------
// K2b: merge 4 channel-group partials -> bb per (b,hw)
// ---------------------------------------------------------------------------
__global__ void k2b_bb() {
    int i = (blockIdx.x * blockDim.x + threadIdx.x) * 4;
    if (i >= BHW) return;
    float4 mx = *(const float4*)(g_pmax + i);
    float4 sm = *(const float4*)(g_pcsm + i);
    #pragma unroll
    for (int cs = 1; cs < CSPLIT; cs++) {
        float4 m2 = *(const float4*)(g_pmax + (size_t)cs * BHW + i);
        float4 s2 = *(const float4*)(g_pcsm + (size_t)cs * BHW + i);
        mx.x = fmaxf(mx.x, m2.x); mx.y = fmaxf(mx.y, m2.y);
        mx.z = fmaxf(mx.z, m2.z); mx.w = fmaxf(mx.w, m2.w);
        sm.x += s2.x; sm.y += s2.y; sm.z += s2.z; sm.w += s2.w;
    }
    float4 bb;
    bb.x = 1.f - expf(-(mx.x - sm.x * (1.0f / CC)));
    bb.y = 1.f - expf(-(mx.y - sm.y * (1.0f / CC)));
    bb.z = 1.f - expf(-(mx.z - sm.z * (1.0f / CC)));
    bb.w = 1.f - expf(-(mx.w - sm.w * (1.0f / CC)));
    *(float4*)(g_bb + i) = bb;
}

// ---------------------------------------------------------------------------
// K3: warp-per-(b,c)-row spatial max/sum of x2 = bb*keep*relu(x).
// bb row (12.5 KB per b) stays in L2 across the 512 channels of that b.
// ---------------------------------------------------------------------------
__global__ void __launch_bounds__(256) k3_stats(const float* __restrict__ x) {
    int gw   = (blockIdx.x * 256 + threadIdx.x) >> 5;   // bc
    int lane = threadIdx.x & 31;
    int b = gw >> 9;
    float keep = g_keep[gw];
    const float4* row = (const float4*)(x + (size_t)gw * HW);
    const float4* bbr = (const float4*)(g_bb + (size_t)b * HW);

    float s = 0.f, m = 0.f;
    #pragma unroll
    for (int i = 0; i < 24; i++) {
        float4 v = row[i * 32 + lane];
        float4 g = bbr[i * 32 + lane];
        float a = g.x * fmaxf(keep * v.x, 0.f);
        float e = g.y * fmaxf(keep * v.y, 0.f);
        float c = g.z * fmaxf(keep * v.z, 0.f);
        float d = g.w * fmaxf(keep * v.w, 0.f);
        s += (a + e) + (c + d);
        m = fmaxf(m, fmaxf(fmaxf(a, e), fmaxf(c, d)));
    }
    if (lane < 16) {
        float4 v = row[768 + lane];
        float4 g = bbr[768 + lane];
        float a = g.x * fmaxf(keep * v.x, 0.f);
        float e = g.y * fmaxf(keep * v.y, 0.f);
        float c = g.z * fmaxf(keep * v.z, 0.f);
        float d = g.w * fmaxf(keep * v.w, 0.f);
        s += (a + e) + (c + d);
        m = fmaxf(m, fmaxf(fmaxf(a, e), fmaxf(c, d)));
    }
    #pragma unroll
    for (int o = 16; o; o >>= 1) {
        s += __shfl_down_sync(0xFFFFFFFFu, s, o);
        m  = fmaxf(m, __shfl_down_sync(0xFFFFFFFFu, m, o));
    }
    if (lane == 0) { g_xmax[gw] = m; g_psum[gw] = s; }
}

// ---------------------------------------------------------------------------
// K4: tiny FC gates -> thres per (b,c)
// ---------------------------------------------------------------------------
__global__ void k4_gates(const float* __restrict__ W1, const float* __restrict__ W3) {
    int b = blockIdx.x;
    __shared__ float pooled[CC];
    int c = threadIdx.x;
    pooled[c] = g_psum[b * CC + c] * (1.0f / HW);
    __syncthreads();
    float d1 = 0.f, d3 = 0.f;
    const float* w1r = W1 + (size_t)c * CC;
    const float* w3r = W3 + (size_t)c * CC;
    #pragma unroll 8
    for (int k = 0; k < CC; k++) {
        float p = pooled[k];
        d1 = fmaf(p, w1r[k], d1);
        d3 = fmaf(p, w3r[k], d3);
    }
    float c1 = 1.f / (1.f + expf(-d1));
    float r3 = fmaxf(d3, 0.f);
    float c3 = (r3 < 1.0f) ? 1.2f : r3;
    g_thres[b * CC + c] = c1 * c3 * g_xmax[b * CC + c];
}

// ---------------------------------------------------------------------------
// K5: final thresholding, recompute x2 from x + bb + keep (bb/keep/thres in L2)
// ---------------------------------------------------------------------------
__global__ void k5_final(const float* __restrict__ x, float* __restrict__ out) {
    unsigned v = blockIdx.x * blockDim.x + threadIdx.x;
    unsigned e = v * 4u;
    if (e >= (unsigned)BB * CC * HW) return;
    unsigned bc  = e / HW;
    unsigned pos = e % HW;
    unsigned b   = bc >> 9;
    float keep = g_keep[bc];
    float th   = g_thres[bc];
    float4 g = *(const float4*)(g_bb + b * HW + pos);
    float4 xv = *(const float4*)(x + e);
    float4 o;
    float t;
    t = g.x * fmaxf(keep * xv.x, 0.f); o.x = (t < th) ? 0.f : t;
    t = g.y * fmaxf(keep * xv.y, 0.f); o.y = (t < th) ? 0.f : t;
    t = g.z * fmaxf(keep * xv.z, 0.f); o.z = (t < th) ? 0.f : t;
    t = g.w * fmaxf(keep * xv.w, 0.f); o.w = (t < th) ? 0.f : t;
    *(float4*)(out + e) = o;
}

// ---------------------------------------------------------------------------
extern "C" void kernel_launch(void* const* d_in, const int* in_sizes, int n_in,
                              void* d_out, int out_size) {
    const float* x  = (const float*)d_in[0];
    const float* W1 = (const float*)d_in[1];
    const float* W3 = (const float*)d_in[2];
    float* out = (float*)d_out;

    k1_keep<<<BC / 8, 256>>>(x);                                    // 2048 blocks, warp/row
    k2_cred<<<dim3((HW + CHUNK - 1) / CHUNK, CSPLIT, BB), 256>>>(x);
    k2b_bb<<<(BHW / 4 + 255) / 256, 256>>>();
    k3_stats<<<BC / 8, 256>>>(x);                                   // 2048 blocks, warp/row
    k4_gates<<<BB, CC>>>(W1, W3);
    unsigned nvec = (unsigned)BB * CC * HW / 4u;
    k5_final<<<(nvec + 255) / 256, 256>>>(x, out);
}

// round 6
// speedup vs baseline: 2.2962x; 2.0537x over previous
#include <cuda_runtime.h>
#include <cuda_bf16.h>

#define BB   32
#define CC   512
#define HH   56
#define WW   56
#define HW   3136            // 56*56
#define HW4  784             // HW/4 float4 per row = 24*32 + 16
#define BC   (BB*CC)         // 16384
#define BHW  (BB*HW)         // 100352
#define CSPLIT 4
#define CGRP  (CC/CSPLIT)    // 128
#define CHUNK 1024           // hw positions per k2 block (256 thr * float4)

__device__ float g_keep[BC];
__device__ float g_xmax[BC];
__device__ float g_psum[BC];
__device__ float g_thres[BC];
__device__ float g_bb[BHW];
__device__ float g_pmax[CSPLIT * BHW];
__device__ float g_pcsm[CSPLIT * BHW];

// ---------------------------------------------------------------------------
// K1: warp-per-(b,c)-row spatial sum/max of relu(x) -> keep mask.
// ---------------------------------------------------------------------------
__global__ void __launch_bounds__(256) k1_keep(const float* __restrict__ x) {
    int gw   = (blockIdx.x * 256 + threadIdx.x) >> 5;   // warp id == bc
    int lane = threadIdx.x & 31;
    const float4* row = (const float4*)(x + (size_t)gw * HW);

    float s = 0.f, m = 0.f;
    #pragma unroll
    for (int i = 0; i < 24; i++) {
        float4 v = row[i * 32 + lane];
        float a = fmaxf(v.x, 0.f), b = fmaxf(v.y, 0.f);
        float c = fmaxf(v.z, 0.f), d = fmaxf(v.w, 0.f);
        s += (a + b) + (c + d);
        m = fmaxf(m, fmaxf(fmaxf(a, b), fmaxf(c, d)));
    }
    if (lane < 16) {
        float4 v = row[768 + lane];
        float a = fmaxf(v.x, 0.f), b = fmaxf(v.y, 0.f);
        float c = fmaxf(v.z, 0.f), d = fmaxf(v.w, 0.f);
        s += (a + b) + (c + d);
        m = fmaxf(m, fmaxf(fmaxf(a, b), fmaxf(c, d)));
    }
    #pragma unroll
    for (int o = 16; o; o >>= 1) {
        s += __shfl_down_sync(0xFFFFFFFFu, s, o);
        m  = fmaxf(m, __shfl_down_sync(0xFFFFFFFFu, m, o));
    }
    if (lane == 0)
        g_keep[gw] = ((m - s * (1.0f / HW)) < 0.5f) ? 0.f : 1.f;
}

// ---------------------------------------------------------------------------
// K2: channel-group partial max/sum of keep*relu(x) at each (b,hw).
// ---------------------------------------------------------------------------
__global__ void __launch_bounds__(256) k2_cred(const float* __restrict__ x) {
    __shared__ float skeep[CGRP];
    int b  = blockIdx.z;
    int cs = blockIdx.y;
    int c0 = cs * CGRP;
    if (threadIdx.x < CGRP) skeep[threadIdx.x] = g_keep[b * CC + c0 + threadIdx.x];
    __syncthreads();

    int pos = blockIdx.x * CHUNK + threadIdx.x * 4;
    if (pos >= HW) return;

    const float* xb = x + ((size_t)b * CC + c0) * HW + pos;
    float4 mx = make_float4(0.f, 0.f, 0.f, 0.f);
    float4 sm = make_float4(0.f, 0.f, 0.f, 0.f);
    #pragma unroll 8
    for (int c = 0; c < CGRP; c++) {
        float4 v = *(const float4*)(xb + (size_t)c * HW);
        float k = skeep[c];
        v.x = fmaxf(k * v.x, 0.f); v.y = fmaxf(k * v.y, 0.f);
        v.z = fmaxf(k * v.z, 0.f); v.w = fmaxf(k * v.w, 0.f);
        mx.x = fmaxf(mx.x, v.x); mx.y = fmaxf(mx.y, v.y);
        mx.z = fmaxf(mx.z, v.z); mx.w = fmaxf(mx.w, v.w);
        sm.x += v.x; sm.y += v.y; sm.z += v.z; sm.w += v.w;
    }
    size_t o = (size_t)cs * BHW + (size_t)b * HW + pos;
    *(float4*)(g_pmax + o) = mx;
    *(float4*)(g_pcsm + o) = sm;
}

// ---------------------------------------------------------------------------
// K2b: merge 4 channel-group partials -> bb per (b,hw)
// ---------------------------------------------------------------------------
__global__ void k2b_bb() {
    int i = (blockIdx.x * blockDim.x + threadIdx.x) * 4;
    if (i >= BHW) return;
    float4 mx = *(const float4*)(g_pmax + i);
    float4 sm = *(const float4*)(g_pcsm + i);
    #pragma unroll
    for (int cs = 1; cs < CSPLIT; cs++) {
        float4 m2 = *(const float4*)(g_pmax + (size_t)cs * BHW + i);
        float4 s2 = *(const float4*)(g_pcsm + (size_t)cs * BHW + i);
        mx.x = fmaxf(mx.x, m2.x); mx.y = fmaxf(mx.y, m2.y);
        mx.z = fmaxf(mx.z, m2.z); mx.w = fmaxf(mx.w, m2.w);
        sm.x += s2.x; sm.y += s2.y; sm.z += s2.z; sm.w += s2.w;
    }
    float4 bb;
    bb.x = 1.f - expf(-(mx.x - sm.x * (1.0f / CC)));
    bb.y = 1.f - expf(-(mx.y - sm.y * (1.0f / CC)));
    bb.z = 1.f - expf(-(mx.z - sm.z * (1.0f / CC)));
    bb.w = 1.f - expf(-(mx.w - sm.w * (1.0f / CC)));
    *(float4*)(g_bb + i) = bb;
}

// ---------------------------------------------------------------------------
// K3: warp-per-(b,c)-row spatial max/sum of x2 = bb*keep*relu(x).
// ---------------------------------------------------------------------------
__global__ void __launch_bounds__(256) k3_stats(const float* __restrict__ x) {
    int gw   = (blockIdx.x * 256 + threadIdx.x) >> 5;   // bc
    int lane = threadIdx.x & 31;
    int b = gw >> 9;
    float keep = g_keep[gw];
    const float4* row = (const float4*)(x + (size_t)gw * HW);
    const float4* bbr = (const float4*)(g_bb + (size_t)b * HW);

    float s = 0.f, m = 0.f;
    #pragma unroll
    for (int i = 0; i < 24; i++) {
        float4 v = row[i * 32 + lane];
        float4 g = bbr[i * 32 + lane];
        float a = g.x * fmaxf(keep * v.x, 0.f);
        float e = g.y * fmaxf(keep * v.y, 0.f);
        float c = g.z * fmaxf(keep * v.z, 0.f);
        float d = g.w * fmaxf(keep * v.w, 0.f);
        s += (a + e) + (c + d);
        m = fmaxf(m, fmaxf(fmaxf(a, e), fmaxf(c, d)));
    }
    if (lane < 16) {
        float4 v = row[768 + lane];
        float4 g = bbr[768 + lane];
        float a = g.x * fmaxf(keep * v.x, 0.f);
        float e = g.y * fmaxf(keep * v.y, 0.f);
        float c = g.z * fmaxf(keep * v.z, 0.f);
        float d = g.w * fmaxf(keep * v.w, 0.f);
        s += (a + e) + (c + d);
        m = fmaxf(m, fmaxf(fmaxf(a, e), fmaxf(c, d)));
    }
    #pragma unroll
    for (int o = 16; o; o >>= 1) {
        s += __shfl_down_sync(0xFFFFFFFFu, s, o);
        m  = fmaxf(m, __shfl_down_sync(0xFFFFFFFFu, m, o));
    }
    if (lane == 0) { g_xmax[gw] = m; g_psum[gw] = s; }
}

// ---------------------------------------------------------------------------
// K4: FC gates, COALESCED: warp per output c, lanes split over k (float4).
// grid = (4 c-quarters, 32 b), block = 512 (16 warps, 8 outputs each).
// Each LDG = 512B contiguous = 4 wavefronts (was 32 lines/LDG before).
// ---------------------------------------------------------------------------
__global__ void __launch_bounds__(512) k4_gates(const float* __restrict__ W1,
                                                const float* __restrict__ W3) {
    int b  = blockIdx.y;
    int cq = blockIdx.x;                 // c-quarter: 0..3
    __shared__ float pooled[CC];
    pooled[threadIdx.x] = g_psum[b * CC + threadIdx.x] * (1.0f / HW);
    __syncthreads();
    const float4* pl4 = (const float4*)pooled;

    int wid = threadIdx.x >> 5, lane = threadIdx.x & 31;
    #pragma unroll
    for (int cc = 0; cc < 8; cc++) {
        int c = (cq << 7) + (wid << 3) + cc;
        const float4* w1r = (const float4*)(W1 + (size_t)c * CC);
        const float4* w3r = (const float4*)(W3 + (size_t)c * CC);
        float d1 = 0.f, d3 = 0.f;
        #pragma unroll
        for (int j = 0; j < 4; j++) {
            int k = lane + (j << 5);     // float4 index 0..127
            float4 p = pl4[k];
            float4 a = w1r[k];
            float4 q = w3r[k];
            d1 = fmaf(a.x, p.x, fmaf(a.y, p.y, fmaf(a.z, p.z, fmaf(a.w, p.w, d1))));
            d3 = fmaf(q.x, p.x, fmaf(q.y, p.y, fmaf(q.z, p.z, fmaf(q.w, p.w, d3))));
        }
        #pragma unroll
        for (int o = 16; o; o >>= 1) {
            d1 += __shfl_down_sync(0xFFFFFFFFu, d1, o);
            d3 += __shfl_down_sync(0xFFFFFFFFu, d3, o);
        }
        if (lane == 0) {
            float c1 = 1.f / (1.f + expf(-d1));
            float r3 = fmaxf(d3, 0.f);
            float c3 = (r3 < 1.0f) ? 1.2f : r3;
            g_thres[b * CC + c] = c1 * c3 * g_xmax[b * CC + c];
        }
    }
}

// ---------------------------------------------------------------------------
// K5: final thresholding, recompute x2 from x + bb + keep
// ---------------------------------------------------------------------------
__global__ void k5_final(const float* __restrict__ x, float* __restrict__ out) {
    unsigned v = blockIdx.x * blockDim.x + threadIdx.x;
    unsigned e = v * 4u;
    if (e >= (unsigned)BB * CC * HW) return;
    unsigned bc  = e / HW;
    unsigned pos = e % HW;
    unsigned b   = bc >> 9;
    float keep = g_keep[bc];
    float th   = g_thres[bc];
    float4 g = *(const float4*)(g_bb + b * HW + pos);
    float4 xv = *(const float4*)(x + e);
    float4 o;
    float t;
    t = g.x * fmaxf(keep * xv.x, 0.f); o.x = (t < th) ? 0.f : t;
    t = g.y * fmaxf(keep * xv.y, 0.f); o.y = (t < th) ? 0.f : t;
    t = g.z * fmaxf(keep * xv.z, 0.f); o.z = (t < th) ? 0.f : t;
    t = g.w * fmaxf(keep * xv.w, 0.f); o.w = (t < th) ? 0.f : t;
    *(float4*)(out + e) = o;
}

// ---------------------------------------------------------------------------
extern "C" void kernel_launch(void* const* d_in, const int* in_sizes, int n_in,
                              void* d_out, int out_size) {
    const float* x  = (const float*)d_in[0];
    const float* W1 = (const float*)d_in[1];
    const float* W3 = (const float*)d_in[2];
    float* out = (float*)d_out;

    k1_keep<<<BC / 8, 256>>>(x);
    k2_cred<<<dim3((HW + CHUNK - 1) / CHUNK, CSPLIT, BB), 256>>>(x);
    k2b_bb<<<(BHW / 4 + 255) / 256, 256>>>();
    k3_stats<<<BC / 8, 256>>>(x);
    k4_gates<<<dim3(4, BB), 512>>>(W1, W3);
    unsigned nvec = (unsigned)BB * CC * HW / 4u;
    k5_final<<<(nvec + 255) / 256, 256>>>(x, out);
}

// round 9
// speedup vs baseline: 2.6784x; 1.1665x over previous
#include <cuda_runtime.h>
#include <cuda_bf16.h>

#define BB   32
#define CC   512
#define HH   56
#define WW   56
#define HW   3136            // 56*56
#define BC   (BB*CC)         // 16384
#define BHW  (BB*HW)         // 100352
#define CSPLIT 4
#define CGRP  (CC/CSPLIT)    // 128
#define CHUNK 1024           // hw positions per K_A/K_C block (256 thr * float4)
#define NCHUNK 4             // ceil(HW/CHUNK)

__device__ float g_keep[BC];
__device__ float g_xmax[BC];
__device__ float g_psum[BC];
__device__ float g_thres[BC];
__device__ float g_bb[BHW];
__device__ float g_pmax[CSPLIT * BHW];   // per-(b,hw) channel-group partial max
__device__ float g_pcsm[CSPLIT * BHW];   // per-(b,hw) channel-group partial sum
__device__ float g_spS[NCHUNK * BC];     // per-(chunk,b,c) spatial partial sum of relu(x)
__device__ float g_spM[NCHUNK * BC];     // per-(chunk,b,c) spatial partial max of relu(x)

// ---------------------------------------------------------------------------
// K_A: ONE pass over x producing BOTH reductions (unmasked):
//  - channel-group partial max/sum of relu(x) per (b,hw)       [k2's job]
//  - spatial partial sum/max of relu(x) per (chunk,b,c)        [k1's job]
// Block: (hw-chunk, c-group, b). Thread owns 4 contiguous hw positions.
// ---------------------------------------------------------------------------
__global__ void __launch_bounds__(256) kA_fused(const float* __restrict__ x) {
    __shared__ float swS[8][CGRP], swM[8][CGRP];
    int b = blockIdx.z, cs = blockIdx.y, chunk = blockIdx.x;
    int c0 = cs * CGRP;
    int pos = chunk * CHUNK + threadIdx.x * 4;
    bool valid = pos < HW;
    const float* xb = x + ((size_t)b * CC + c0) * HW + pos;
    int wid = threadIdx.x >> 5, lane = threadIdx.x & 31;

    float4 mx = make_float4(0.f, 0.f, 0.f, 0.f);
    float4 sm = make_float4(0.f, 0.f, 0.f, 0.f);
    #pragma unroll 4
    for (int c = 0; c < CGRP; c++) {
        float4 v = make_float4(0.f, 0.f, 0.f, 0.f);
        if (valid) v = *(const float4*)(xb + (size_t)c * HW);
        v.x = fmaxf(v.x, 0.f); v.y = fmaxf(v.y, 0.f);
        v.z = fmaxf(v.z, 0.f); v.w = fmaxf(v.w, 0.f);
        // channel-direction accumulation (per hw position)
        mx.x = fmaxf(mx.x, v.x); mx.y = fmaxf(mx.y, v.y);
        mx.z = fmaxf(mx.z, v.z); mx.w = fmaxf(mx.w, v.w);
        sm.x += v.x; sm.y += v.y; sm.z += v.z; sm.w += v.w;
        // spatial-direction partial for this c: warp-reduce 128 positions
        float ts = (v.x + v.y) + (v.z + v.w);
        float tm = fmaxf(fmaxf(v.x, v.y), fmaxf(v.z, v.w));
        #pragma unroll
        for (int o = 16; o; o >>= 1) {
            ts += __shfl_down_sync(0xFFFFFFFFu, ts, o);
            tm  = fmaxf(tm, __shfl_down_sync(0xFFFFFFFFu, tm, o));
        }
        if (lane == 0) { swS[wid][c] = ts; swM[wid][c] = tm; }
    }
    if (valid) {
        size_t o = (size_t)cs * BHW + (size_t)b * HW + pos;
        *(float4*)(g_pmax + o) = mx;
        *(float4*)(g_pcsm + o) = sm;
    }
    __syncthreads();
    if (threadIdx.x < CGRP) {
        int c = threadIdx.x;
        float S = 0.f, M = 0.f;
        #pragma unroll
        for (int w = 0; w < 8; w++) { S += swS[w][c]; M = fmaxf(M, swM[w][c]); }
        int idx = chunk * BC + b * CC + c0 + c;
        g_spS[idx] = S;
        g_spM[idx] = M;
    }
}

// ---------------------------------------------------------------------------
// K_C: derive keep from spatial partials; if ANY channel in this (b,cs) group
// is dropped (rare), recompute that group's channel partials MASKED.
// Fast path: clean group -> immediate exit (unmasked partials already valid).
// ---------------------------------------------------------------------------
__global__ void __launch_bounds__(256) kC_fixup(const float* __restrict__ x) {
    __shared__ float skeep[CGRP];
    int b = blockIdx.z, cs = blockIdx.y, chunk = blockIdx.x;
    int c0 = cs * CGRP;
    int t = threadIdx.x;

    float mykeep = 1.f;
    if (t < CGRP) {
        int bc = b * CC + c0 + t;
        float S = 0.f, M = 0.f;
        #pragma unroll
        for (int ch = 0; ch < NCHUNK; ch++) {
            S += g_spS[ch * BC + bc];
            M  = fmaxf(M, g_spM[ch * BC + bc]);
        }
        mykeep = ((M - S * (1.0f / HW)) < 0.5f) ? 0.f : 1.f;
        skeep[t] = mykeep;
        if (chunk == 0) g_keep[bc] = mykeep;
    }
    int clean = __syncthreads_and(mykeep != 0.f);
    if (clean) return;

    // dirty group: recompute masked channel partials for this chunk
    int pos = chunk * CHUNK + t * 4;
    if (pos >= HW) return;
    const float* xb = x + ((size_t)b * CC + c0) * HW + pos;
    float4 mx = make_float4(0.f, 0.f, 0.f, 0.f);
    float4 sm = make_float4(0.f, 0.f, 0.f, 0.f);
    #pragma unroll 8
    for (int c = 0; c < CGRP; c++) {
        float4 v = *(const float4*)(xb + (size_t)c * HW);
        float k = skeep[c];
        v.x = fmaxf(k * v.x, 0.f); v.y = fmaxf(k * v.y, 0.f);
        v.z = fmaxf(k * v.z, 0.f); v.w = fmaxf(k * v.w, 0.f);
        mx.x = fmaxf(mx.x, v.x); mx.y = fmaxf(mx.y, v.y);
        mx.z = fmaxf(mx.z, v.z); mx.w = fmaxf(mx.w, v.w);
        sm.x += v.x; sm.y += v.y; sm.z += v.z; sm.w += v.w;
    }
    size_t o = (size_t)cs * BHW + (size_t)b * HW + pos;
    *(float4*)(g_pmax + o) = mx;
    *(float4*)(g_pcsm + o) = sm;
}

// ---------------------------------------------------------------------------
// K2b: merge 4 channel-group partials -> bb per (b,hw)
// ---------------------------------------------------------------------------
__global__ void k2b_bb() {
    int i = (blockIdx.x * blockDim.x + threadIdx.x) * 4;
    if (i >= BHW) return;
    float4 mx = *(const float4*)(g_pmax + i);
    float4 sm = *(const float4*)(g_pcsm + i);
    #pragma unroll
    for (int cs = 1; cs < CSPLIT; cs++) {
        float4 m2 = *(const float4*)(g_pmax + (size_t)cs * BHW + i);
        float4 s2 = *(const float4*)(g_pcsm + (size_t)cs * BHW + i);
        mx.x = fmaxf(mx.x, m2.x); mx.y = fmaxf(mx.y, m2.y);
        mx.z = fmaxf(mx.z, m2.z); mx.w = fmaxf(mx.w, m2.w);
        sm.x += s2.x; sm.y += s2.y; sm.z += s2.z; sm.w += s2.w;
    }
    float4 bb;
    bb.x = 1.f - expf(-(mx.x - sm.x * (1.0f / CC)));
    bb.y = 1.f - expf(-(mx.y - sm.y * (1.0f / CC)));
    bb.z = 1.f - expf(-(mx.z - sm.z * (1.0f / CC)));
    bb.w = 1.f - expf(-(mx.w - sm.w * (1.0f / CC)));
    *(float4*)(g_bb + i) = bb;
}

// ---------------------------------------------------------------------------
// K3: warp-per-(b,c)-row spatial max/sum of x2 = bb*keep*relu(x).
// ---------------------------------------------------------------------------
__global__ void __launch_bounds__(256) k3_stats(const float* __restrict__ x) {
    int gw   = (blockIdx.x * 256 + threadIdx.x) >> 5;   // bc
    int lane = threadIdx.x & 31;
    int b = gw >> 9;
    float keep = g_keep[gw];
    const float4* row = (const float4*)(x + (size_t)gw * HW);
    const float4* bbr = (const float4*)(g_bb + (size_t)b * HW);

    float s = 0.f, m = 0.f;
    #pragma unroll
    for (int i = 0; i < 24; i++) {
        float4 v = row[i * 32 + lane];
        float4 g = bbr[i * 32 + lane];
        float a = g.x * fmaxf(keep * v.x, 0.f);
        float e = g.y * fmaxf(keep * v.y, 0.f);
        float c = g.z * fmaxf(keep * v.z, 0.f);
        float d = g.w * fmaxf(keep * v.w, 0.f);
        s += (a + e) + (c + d);
        m = fmaxf(m, fmaxf(fmaxf(a, e), fmaxf(c, d)));
    }
    if (lane < 16) {
        float4 v = row[768 + lane];
        float4 g = bbr[768 + lane];
        float a = g.x * fmaxf(keep * v.x, 0.f);
        float e = g.y * fmaxf(keep * v.y, 0.f);
        float c = g.z * fmaxf(keep * v.z, 0.f);
        float d = g.w * fmaxf(keep * v.w, 0.f);
        s += (a + e) + (c + d);
        m = fmaxf(m, fmaxf(fmaxf(a, e), fmaxf(c, d)));
    }
    #pragma unroll
    for (int o = 16; o; o >>= 1) {
        s += __shfl_down_sync(0xFFFFFFFFu, s, o);
        m  = fmaxf(m, __shfl_down_sync(0xFFFFFFFFu, m, o));
    }
    if (lane == 0) { g_xmax[gw] = m; g_psum[gw] = s; }
}

// ---------------------------------------------------------------------------
// K4: FC gates, coalesced: warp per output c, lanes split over k (float4).
// ---------------------------------------------------------------------------
__global__ void __launch_bounds__(512) k4_gates(const float* __restrict__ W1,
                                                const float* __restrict__ W3) {
    int b  = blockIdx.y;
    int cq = blockIdx.x;                 // c-quarter: 0..3
    __shared__ float pooled[CC];
    pooled[threadIdx.x] = g_psum[b * CC + threadIdx.x] * (1.0f / HW);
    __syncthreads();
    const float4* pl4 = (const float4*)pooled;

    int wid = threadIdx.x >> 5, lane = threadIdx.x & 31;
    #pragma unroll
    for (int cc = 0; cc < 8; cc++) {
        int c = (cq << 7) + (wid << 3) + cc;
        const float4* w1r = (const float4*)(W1 + (size_t)c * CC);
        const float4* w3r = (const float4*)(W3 + (size_t)c * CC);
        float d1 = 0.f, d3 = 0.f;
        #pragma unroll
        for (int j = 0; j < 4; j++) {
            int k = lane + (j << 5);     // float4 index 0..127
            float4 p = pl4[k];
            float4 a = w1r[k];
            float4 q = w3r[k];
            d1 = fmaf(a.x, p.x, fmaf(a.y, p.y, fmaf(a.z, p.z, fmaf(a.w, p.w, d1))));
            d3 = fmaf(q.x, p.x, fmaf(q.y, p.y, fmaf(q.z, p.z, fmaf(q.w, p.w, d3))));
        }
        #pragma unroll
        for (int o = 16; o; o >>= 1) {
            d1 += __shfl_down_sync(0xFFFFFFFFu, d1, o);
            d3 += __shfl_down_sync(0xFFFFFFFFu, d3, o);
        }
        if (lane == 0) {
            float c1 = 1.f / (1.f + expf(-d1));
            float r3 = fmaxf(d3, 0.f);
            float c3 = (r3 < 1.0f) ? 1.2f : r3;
            g_thres[b * CC + c] = c1 * c3 * g_xmax[b * CC + c];
        }
    }
}

// ---------------------------------------------------------------------------
// K5: final thresholding, recompute x2 from x + bb + keep
// ---------------------------------------------------------------------------
__global__ void k5_final(const float* __restrict__ x, float* __restrict__ out) {
    unsigned v = blockIdx.x * blockDim.x + threadIdx.x;
    unsigned e = v * 4u;
    if (e >= (unsigned)BB * CC * HW) return;
    unsigned bc  = e / HW;
    unsigned pos = e % HW;
    unsigned b   = bc >> 9;
    float keep = g_keep[bc];
    float th   = g_thres[bc];
    float4 g = *(const float4*)(g_bb + b * HW + pos);
    float4 xv = *(const float4*)(x + e);
    float4 o;
    float t;
    t = g.x * fmaxf(keep * xv.x, 0.f); o.x = (t < th) ? 0.f : t;
    t = g.y * fmaxf(keep * xv.y, 0.f); o.y = (t < th) ? 0.f : t;
    t = g.z * fmaxf(keep * xv.z, 0.f); o.z = (t < th) ? 0.f : t;
    t = g.w * fmaxf(keep * xv.w, 0.f); o.w = (t < th) ? 0.f : t;
    *(float4*)(out + e) = o;
}

// ---------------------------------------------------------------------------
extern "C" void kernel_launch(void* const* d_in, const int* in_sizes, int n_in,
                              void* d_out, int out_size) {
    const float* x  = (const float*)d_in[0];
    const float* W1 = (const float*)d_in[1];
    const float* W3 = (const float*)d_in[2];
    float* out = (float*)d_out;

    dim3 gA(NCHUNK, CSPLIT, BB);                 // (4,4,32) = 512 blocks
    kA_fused<<<gA, 256>>>(x);
    kC_fixup<<<gA, 256>>>(x);
    k2b_bb<<<(BHW / 4 + 255) / 256, 256>>>();
    k3_stats<<<BC / 8, 256>>>(x);
    k4_gates<<<dim3(4, BB), 512>>>(W1, W3);
    unsigned nvec = (unsigned)BB * CC * HW / 4u;
    k5_final<<<(nvec + 255) / 256, 256>>>(x, out);
}

// round 12
// speedup vs baseline: 2.7727x; 1.0352x over previous
#include <cuda_runtime.h>
#include <cuda_bf16.h>

#define BB   32
#define CC   512
#define HH   56
#define WW   56
#define HW   3136            // 56*56
#define BC   (BB*CC)         // 16384
#define BHW  (BB*HW)         // 100352
#define CSPLIT 4
#define CGRP  (CC/CSPLIT)    // 128
#define CHUNK 1024           // hw positions per K_A/K_C block (256 thr * float4)
#define NCHUNK 4             // ceil(HW/CHUNK)

__device__ float g_keep[BC];
__device__ float g_xmax[BC];
__device__ float g_psum[BC];
__device__ float g_thres[BC];
__device__ float g_bb[BHW];
__device__ float g_pmax[CSPLIT * BHW];   // per-(b,hw) channel-group partial max
__device__ float g_pcsm[CSPLIT * BHW];   // per-(b,hw) channel-group partial sum
__device__ float g_spS[NCHUNK * BC];     // per-(chunk,b,c) spatial partial sum of relu(x)
__device__ float g_spM[NCHUNK * BC];     // per-(chunk,b,c) spatial partial max of relu(x)

// single-instruction warp max for NON-NEGATIVE floats: for v >= 0, IEEE float
// ordering == unsigned ordering of the bit pattern. redux.sync.max.u32 is sm_80+.
__device__ __forceinline__ float warp_max_nonneg(float v) {
    unsigned r;
    asm("redux.sync.max.u32 %0, %1, 0xffffffff;" : "=r"(r) : "r"(__float_as_uint(v)));
    return __uint_as_float(r);
}

// ---------------------------------------------------------------------------
// K_A: ONE pass over x producing BOTH reductions (unmasked):
//  - channel-group partial max/sum of relu(x) per (b,hw)
//  - spatial partial sum/max of relu(x) per (chunk,b,c)
// ---------------------------------------------------------------------------
__global__ void __launch_bounds__(256) kA_fused(const float* __restrict__ x) {
    __shared__ float swS[8][CGRP], swM[8][CGRP];
    int b = blockIdx.z, cs = blockIdx.y, chunk = blockIdx.x;
    int c0 = cs * CGRP;
    int pos = chunk * CHUNK + threadIdx.x * 4;
    bool valid = pos < HW;
    const float* xb = x + ((size_t)b * CC + c0) * HW + pos;
    int wid = threadIdx.x >> 5, lane = threadIdx.x & 31;

    float4 mx = make_float4(0.f, 0.f, 0.f, 0.f);
    float4 sm = make_float4(0.f, 0.f, 0.f, 0.f);
    #pragma unroll 4
    for (int c = 0; c < CGRP; c++) {
        float4 v = make_float4(0.f, 0.f, 0.f, 0.f);
        if (valid) v = *(const float4*)(xb + (size_t)c * HW);
        v.x = fmaxf(v.x, 0.f); v.y = fmaxf(v.y, 0.f);
        v.z = fmaxf(v.z, 0.f); v.w = fmaxf(v.w, 0.f);
        // channel-direction accumulation (per hw position)
        mx.x = fmaxf(mx.x, v.x); mx.y = fmaxf(mx.y, v.y);
        mx.z = fmaxf(mx.z, v.z); mx.w = fmaxf(mx.w, v.w);
        sm.x += v.x; sm.y += v.y; sm.z += v.z; sm.w += v.w;
        // spatial-direction partial for this c: warp-reduce 128 positions
        float ts = (v.x + v.y) + (v.z + v.w);
        float tm = fmaxf(fmaxf(v.x, v.y), fmaxf(v.z, v.w));
        #pragma unroll
        for (int o = 16; o; o >>= 1)
            ts += __shfl_down_sync(0xFFFFFFFFu, ts, o);
        tm = warp_max_nonneg(tm);
        if (lane == 0) { swS[wid][c] = ts; swM[wid][c] = tm; }
    }
    if (valid) {
        size_t o = (size_t)cs * BHW + (size_t)b * HW + pos;
        *(float4*)(g_pmax + o) = mx;
        *(float4*)(g_pcsm + o) = sm;
    }
    __syncthreads();
    if (threadIdx.x < CGRP) {
        int c = threadIdx.x;
        float S = 0.f, M = 0.f;
        #pragma unroll
        for (int w = 0; w < 8; w++) { S += swS[w][c]; M = fmaxf(M, swM[w][c]); }
        int idx = chunk * BC + b * CC + c0 + c;
        g_spS[idx] = S;
        g_spM[idx] = M;
    }
}

// ---------------------------------------------------------------------------
// K_C: derive keep from spatial partials; recompute masked partials only for
// dirty (b,cs) groups (rare). Clean -> immediate exit.
// ---------------------------------------------------------------------------
__global__ void __launch_bounds__(256) kC_fixup(const float* __restrict__ x) {
    __shared__ float skeep[CGRP];
    int b = blockIdx.z, cs = blockIdx.y, chunk = blockIdx.x;
    int c0 = cs * CGRP;
    int t = threadIdx.x;

    float mykeep = 1.f;
    if (t < CGRP) {
        int bc = b * CC + c0 + t;
        float S = 0.f, M = 0.f;
        #pragma unroll
        for (int ch = 0; ch < NCHUNK; ch++) {
            S += g_spS[ch * BC + bc];
            M  = fmaxf(M, g_spM[ch * BC + bc]);
        }
        mykeep = ((M - S * (1.0f / HW)) < 0.5f) ? 0.f : 1.f;
        skeep[t] = mykeep;
        if (chunk == 0) g_keep[bc] = mykeep;
    }
    int clean = __syncthreads_and(mykeep != 0.f);
    if (clean) return;

    int pos = chunk * CHUNK + t * 4;
    if (pos >= HW) return;
    const float* xb = x + ((size_t)b * CC + c0) * HW + pos;
    float4 mx = make_float4(0.f, 0.f, 0.f, 0.f);
    float4 sm = make_float4(0.f, 0.f, 0.f, 0.f);
    #pragma unroll 8
    for (int c = 0; c < CGRP; c++) {
        float4 v = *(const float4*)(xb + (size_t)c * HW);
        float k = skeep[c];
        v.x = fmaxf(k * v.x, 0.f); v.y = fmaxf(k * v.y, 0.f);
        v.z = fmaxf(k * v.z, 0.f); v.w = fmaxf(k * v.w, 0.f);
        mx.x = fmaxf(mx.x, v.x); mx.y = fmaxf(mx.y, v.y);
        mx.z = fmaxf(mx.z, v.z); mx.w = fmaxf(mx.w, v.w);
        sm.x += v.x; sm.y += v.y; sm.z += v.z; sm.w += v.w;
    }
    size_t o = (size_t)cs * BHW + (size_t)b * HW + pos;
    *(float4*)(g_pmax + o) = mx;
    *(float4*)(g_pcsm + o) = sm;
}

// ---------------------------------------------------------------------------
// K2b: merge 4 channel-group partials -> bb per (b,hw)
// ---------------------------------------------------------------------------
__global__ void k2b_bb() {
    int i = (blockIdx.x * blockDim.x + threadIdx.x) * 4;
    if (i >= BHW) return;
    float4 mx = *(const float4*)(g_pmax + i);
    float4 sm = *(const float4*)(g_pcsm + i);
    #pragma unroll
    for (int cs = 1; cs < CSPLIT; cs++) {
        float4 m2 = *(const float4*)(g_pmax + (size_t)cs * BHW + i);
        float4 s2 = *(const float4*)(g_pcsm + (size_t)cs * BHW + i);
        mx.x = fmaxf(mx.x, m2.x); mx.y = fmaxf(mx.y, m2.y);
        mx.z = fmaxf(mx.z, m2.z); mx.w = fmaxf(mx.w, m2.w);
        sm.x += s2.x; sm.y += s2.y; sm.z += s2.z; sm.w += s2.w;
    }
    float4 bb;
    bb.x = 1.f - expf(-(mx.x - sm.x * (1.0f / CC)));
    bb.y = 1.f - expf(-(mx.y - sm.y * (1.0f / CC)));
    bb.z = 1.f - expf(-(mx.z - sm.z * (1.0f / CC)));
    bb.w = 1.f - expf(-(mx.w - sm.w * (1.0f / CC)));
    *(float4*)(g_bb + i) = bb;
}

// ---------------------------------------------------------------------------
// K3: warp-per-(b,c)-row spatial max/sum of x2 = bb*keep*relu(x).
// ---------------------------------------------------------------------------
__global__ void __launch_bounds__(256) k3_stats(const float* __restrict__ x) {
    int gw   = (blockIdx.x * 256 + threadIdx.x) >> 5;   // bc
    int lane = threadIdx.x & 31;
    int b = gw >> 9;
    float keep = g_keep[gw];
    const float4* row = (const float4*)(x + (size_t)gw * HW);
    const float4* bbr = (const float4*)(g_bb + (size_t)b * HW);

    float s = 0.f, m = 0.f;
    #pragma unroll
    for (int i = 0; i < 24; i++) {
        float4 v = row[i * 32 + lane];
        float4 g = bbr[i * 32 + lane];
        float a = g.x * fmaxf(keep * v.x, 0.f);
        float e = g.y * fmaxf(keep * v.y, 0.f);
        float c = g.z * fmaxf(keep * v.z, 0.f);
        float d = g.w * fmaxf(keep * v.w, 0.f);
        s += (a + e) + (c + d);
        m = fmaxf(m, fmaxf(fmaxf(a, e), fmaxf(c, d)));
    }
    if (lane < 16) {
        float4 v = row[768 + lane];
        float4 g = bbr[768 + lane];
        float a = g.x * fmaxf(keep * v.x, 0.f);
        float e = g.y * fmaxf(keep * v.y, 0.f);
        float c = g.z * fmaxf(keep * v.z, 0.f);
        float d = g.w * fmaxf(keep * v.w, 0.f);
        s += (a + e) + (c + d);
        m = fmaxf(m, fmaxf(fmaxf(a, e), fmaxf(c, d)));
    }
    #pragma unroll
    for (int o = 16; o; o >>= 1)
        s += __shfl_down_sync(0xFFFFFFFFu, s, o);
    m = warp_max_nonneg(m);
    if (lane == 0) { g_xmax[gw] = m; g_psum[gw] = s; }
}

// ---------------------------------------------------------------------------
// K4: FC gates, coalesced: warp per output c, lanes split over k (float4).
// ---------------------------------------------------------------------------
__global__ void __launch_bounds__(512) k4_gates(const float* __restrict__ W1,
                                                const float* __restrict__ W3) {
    int b  = blockIdx.y;
    int cq = blockIdx.x;                 // c-quarter: 0..3
    __shared__ float pooled[CC];
    pooled[threadIdx.x] = g_psum[b * CC + threadIdx.x] * (1.0f / HW);
    __syncthreads();
    const float4* pl4 = (const float4*)pooled;

    int wid = threadIdx.x >> 5, lane = threadIdx.x & 31;
    #pragma unroll
    for (int cc = 0; cc < 8; cc++) {
        int c = (cq << 7) + (wid << 3) + cc;
        const float4* w1r = (const float4*)(W1 + (size_t)c * CC);
        const float4* w3r = (const float4*)(W3 + (size_t)c * CC);
        float d1 = 0.f, d3 = 0.f;
        #pragma unroll
        for (int j = 0; j < 4; j++) {
            int k = lane + (j << 5);
            float4 p = pl4[k];
            float4 a = w1r[k];
            float4 q = w3r[k];
            d1 = fmaf(a.x, p.x, fmaf(a.y, p.y, fmaf(a.z, p.z, fmaf(a.w, p.w, d1))));
            d3 = fmaf(q.x, p.x, fmaf(q.y, p.y, fmaf(q.z, p.z, fmaf(q.w, p.w, d3))));
        }
        #pragma unroll
        for (int o = 16; o; o >>= 1) {
            d1 += __shfl_down_sync(0xFFFFFFFFu, d1, o);
            d3 += __shfl_down_sync(0xFFFFFFFFu, d3, o);
        }
        if (lane == 0) {
            float c1 = 1.f / (1.f + expf(-d1));
            float r3 = fmaxf(d3, 0.f);
            float c3 = (r3 < 1.0f) ? 1.2f : r3;
            g_thres[b * CC + c] = c1 * c3 * g_xmax[b * CC + c];
        }
    }
}

// ---------------------------------------------------------------------------
// K5: final thresholding, recompute x2 from x + bb + keep
// ---------------------------------------------------------------------------
__global__ void k5_final(const float* __restrict__ x, float* __restrict__ out) {
    unsigned v = blockIdx.x * blockDim.x + threadIdx.x;
    unsigned e = v * 4u;
    if (e >= (unsigned)BB * CC * HW) return;
    unsigned bc  = e / HW;
    unsigned pos = e % HW;
    unsigned b   = bc >> 9;
    float keep = g_keep[bc];
    float th   = g_thres[bc];
    float4 g = *(const float4*)(g_bb + b * HW + pos);
    float4 xv = *(const float4*)(x + e);
    float4 o;
    float t;
    t = g.x * fmaxf(keep * xv.x, 0.f); o.x = (t < th) ? 0.f : t;
    t = g.y * fmaxf(keep * xv.y, 0.f); o.y = (t < th) ? 0.f : t;
    t = g.z * fmaxf(keep * xv.z, 0.f); o.z = (t < th) ? 0.f : t;
    t = g.w * fmaxf(keep * xv.w, 0.f); o.w = (t < th) ? 0.f : t;
    *(float4*)(out + e) = o;
}

// ---------------------------------------------------------------------------
extern "C" void kernel_launch(void* const* d_in, const int* in_sizes, int n_in,
                              void* d_out, int out_size) {
    const float* x  = (const float*)d_in[0];
    const float* W1 = (const float*)d_in[1];
    const float* W3 = (const float*)d_in[2];
    float* out = (float*)d_out;

    dim3 gA(NCHUNK, CSPLIT, BB);                 // (4,4,32) = 512 blocks
    kA_fused<<<gA, 256>>>(x);
    kC_fixup<<<gA, 256>>>(x);
    k2b_bb<<<(BHW / 4 + 255) / 256, 256>>>();
    k3_stats<<<BC / 8, 256>>>(x);
    k4_gates<<<dim3(4, BB), 512>>>(W1, W3);
    unsigned nvec = (unsigned)BB * CC * HW / 4u;
    k5_final<<<(nvec + 255) / 256, 256>>>(x, out);
}

// round 15
// speedup vs baseline: 2.9087x; 1.0490x over previous
#include <cuda_runtime.h>
#include <cuda_bf16.h>

#define BB   32
#define CC   512
#define HW   3136            // 56*56
#define BC   (BB*CC)         // 16384
#define BHW  (BB*HW)         // 100352
#define CSPLIT 4
#define CGRP  (CC/CSPLIT)    // 128
#define CHUNK 1024           // hw positions per phase-A block
#define NCHUNK 4
#define NBLK 512
#define NTHR 256

__device__ float g_keep[BC];
__device__ float g_xmax[BC];
__device__ float g_psum[BC];
__device__ float g_thres[BC];
__device__ float g_bb[BHW];
__device__ float g_pmax[CSPLIT * BHW];
__device__ float g_pcsm[CSPLIT * BHW];
__device__ float g_spS[NCHUNK * BC];
__device__ float g_spM[NCHUNK * BC];
__device__ unsigned g_count;   // zero-init; returns to 0 after each barrier
__device__ unsigned g_gen;     // monotonic across replays (generation barrier)

// single-instruction warp max for NON-NEGATIVE floats (u32 redux, sm_80+)
__device__ __forceinline__ float warp_max_nonneg(float v) {
    unsigned r;
    asm("redux.sync.max.u32 %0, %1, 0xffffffff;" : "=r"(r) : "r"(__float_as_uint(v)));
    return __uint_as_float(r);
}

// Grid-wide barrier: all NBLK blocks resident by construction (launch_bounds(256,4)
// -> 4 CTAs/SM * 148 SMs = 592 >= 512). Generation counter => replay-safe.
__device__ __forceinline__ void grid_barrier() {
    __syncthreads();
    __threadfence();
    if (threadIdx.x == 0) {
        unsigned my = atomicAdd(&g_gen, 0u);          // acquire-read gen BEFORE arriving
        if (atomicAdd(&g_count, 1u) == NBLK - 1) {
            atomicExch(&g_count, 0u);
            __threadfence();
            atomicAdd(&g_gen, 1u);                    // release
        } else {
            while (atomicAdd(&g_gen, 0u) == my) { }   // acquire spin
        }
    }
    __syncthreads();
}

__global__ void __launch_bounds__(NTHR, 4) pam_persistent(
    const float* __restrict__ x, const float* __restrict__ W1,
    const float* __restrict__ W3, float* __restrict__ out)
{
    __shared__ float sh[2048];     // 8KB, reused per phase
    __shared__ int   sdirty[CSPLIT];

    const int bid  = blockIdx.x;
    const int t    = threadIdx.x;
    const int wid  = t >> 5, lane = t & 31;

    // ========================= PHASE A ====================================
    // Unmasked dual reduction: channel-group partials per (b,hw) + spatial
    // partials per (chunk,b,c). Logical grid: chunk=bid&3, cs=(bid>>2)&3, b=bid>>4.
    {
        float (*swS)[CGRP] = (float(*)[CGRP])sh;           // [8][128]
        float (*swM)[CGRP] = (float(*)[CGRP])(sh + 1024);  // [8][128]
        int chunk = bid & 3, cs = (bid >> 2) & 3, b = bid >> 4;
        int c0 = cs * CGRP;
        int pos = chunk * CHUNK + t * 4;
        bool valid = pos < HW;
        const float* xb = x + ((size_t)b * CC + c0) * HW + pos;

        float4 mx = make_float4(0.f, 0.f, 0.f, 0.f);
        float4 sm = make_float4(0.f, 0.f, 0.f, 0.f);
        #pragma unroll 4
        for (int c = 0; c < CGRP; c++) {
            float4 v = make_float4(0.f, 0.f, 0.f, 0.f);
            if (valid) v = *(const float4*)(xb + (size_t)c * HW);
            v.x = fmaxf(v.x, 0.f); v.y = fmaxf(v.y, 0.f);
            v.z = fmaxf(v.z, 0.f); v.w = fmaxf(v.w, 0.f);
            mx.x = fmaxf(mx.x, v.x); mx.y = fmaxf(mx.y, v.y);
            mx.z = fmaxf(mx.z, v.z); mx.w = fmaxf(mx.w, v.w);
            sm.x += v.x; sm.y += v.y; sm.z += v.z; sm.w += v.w;
            float ts = (v.x + v.y) + (v.z + v.w);
            float tm = fmaxf(fmaxf(v.x, v.y), fmaxf(v.z, v.w));
            #pragma unroll
            for (int o = 16; o; o >>= 1)
                ts += __shfl_down_sync(0xFFFFFFFFu, ts, o);
            tm = warp_max_nonneg(tm);
            if (lane == 0) { swS[wid][c] = ts; swM[wid][c] = tm; }
        }
        if (valid) {
            size_t o = (size_t)cs * BHW + (size_t)b * HW + pos;
            *(float4*)(g_pmax + o) = mx;
            *(float4*)(g_pcsm + o) = sm;
        }
        __syncthreads();
        if (t < CGRP) {
            float S = 0.f, M = 0.f;
            #pragma unroll
            for (int w = 0; w < 8; w++) { S += swS[w][t]; M = fmaxf(M, swM[w][t]); }
            int idx = chunk * BC + b * CC + c0 + t;
            g_spS[idx] = S;
            g_spM[idx] = M;
        }
    }
    grid_barrier();

    // ========================= PHASE C ====================================
    // keep derivation + dirty-group masked fixup + partial merge -> bb.
    // Logical grid: 128 units (chunk=bid&3, b=bid>>2); blocks >=128 idle.
    if (bid < NCHUNK * BB) {
        float (*skeep)[CGRP] = (float(*)[CGRP])sh;         // [4][128]
        int chunk = bid & 3, b = bid >> 2;
        if (t < CSPLIT) sdirty[t] = 0;
        __syncthreads();
        // keep for all 512 channels of this b (threads 0..127 per cs group)
        #pragma unroll
        for (int cs = 0; cs < CSPLIT; cs++) {
            if (t < CGRP) {
                int bc = b * CC + cs * CGRP + t;
                float S = 0.f, M = 0.f;
                #pragma unroll
                for (int ch = 0; ch < NCHUNK; ch++) {
                    S += g_spS[ch * BC + bc];
                    M  = fmaxf(M, g_spM[ch * BC + bc]);
                }
                float kp = ((M - S * (1.0f / HW)) < 0.5f) ? 0.f : 1.f;
                skeep[cs][t] = kp;
                if (chunk == 0) g_keep[bc] = kp;
                if (kp == 0.f) atomicOr(&sdirty[cs], 1);
            }
        }
        __syncthreads();

        int pos = chunk * CHUNK + t * 4;
        bool valid = pos < HW;
        // fixup: recompute masked partials for dirty groups (rare)
        #pragma unroll
        for (int cs = 0; cs < CSPLIT; cs++) {
            if (sdirty[cs] && valid) {
                const float* xb = x + ((size_t)b * CC + cs * CGRP) * HW + pos;
                float4 mx = make_float4(0.f, 0.f, 0.f, 0.f);
                float4 sm = make_float4(0.f, 0.f, 0.f, 0.f);
                #pragma unroll 8
                for (int c = 0; c < CGRP; c++) {
                    float4 v = *(const float4*)(xb + (size_t)c * HW);
                    float k = skeep[cs][c];
                    v.x = fmaxf(k * v.x, 0.f); v.y = fmaxf(k * v.y, 0.f);
                    v.z = fmaxf(k * v.z, 0.f); v.w = fmaxf(k * v.w, 0.f);
                    mx.x = fmaxf(mx.x, v.x); mx.y = fmaxf(mx.y, v.y);
                    mx.z = fmaxf(mx.z, v.z); mx.w = fmaxf(mx.w, v.w);
                    sm.x += v.x; sm.y += v.y; sm.z += v.z; sm.w += v.w;
                }
                size_t o = (size_t)cs * BHW + (size_t)b * HW + pos;
                *(float4*)(g_pmax + o) = mx;   // same-thread readback below
                *(float4*)(g_pcsm + o) = sm;
            }
        }
        // merge partials -> bb (same thread covers same pos as fixup)
        if (valid) {
            size_t base = (size_t)b * HW + pos;
            float4 mx = *(const float4*)(g_pmax + base);
            float4 sm = *(const float4*)(g_pcsm + base);
            #pragma unroll
            for (int cs = 1; cs < CSPLIT; cs++) {
                float4 m2 = *(const float4*)(g_pmax + (size_t)cs * BHW + base);
                float4 s2 = *(const float4*)(g_pcsm + (size_t)cs * BHW + base);
                mx.x = fmaxf(mx.x, m2.x); mx.y = fmaxf(mx.y, m2.y);
                mx.z = fmaxf(mx.z, m2.z); mx.w = fmaxf(mx.w, m2.w);
                sm.x += s2.x; sm.y += s2.y; sm.z += s2.z; sm.w += s2.w;
            }
            float4 bb;
            bb.x = 1.f - expf(-(mx.x - sm.x * (1.0f / CC)));
            bb.y = 1.f - expf(-(mx.y - sm.y * (1.0f / CC)));
            bb.z = 1.f - expf(-(mx.z - sm.z * (1.0f / CC)));
            bb.w = 1.f - expf(-(mx.w - sm.w * (1.0f / CC)));
            *(float4*)(g_bb + base) = bb;
        }
    }
    grid_barrier();

    // ========================= PHASE K3 ===================================
    // warp-per-(b,c)-row spatial max/sum of x2 = bb*keep*relu(x).
    // Real block covers 32 CONSECUTIVE bc (one 128B line of g_xmax/g_psum).
    {
        #pragma unroll
        for (int j = 0; j < 4; j++) {
            int gw = bid * 32 + j * 8 + wid;     // bc
            int b = gw >> 9;
            float keep = g_keep[gw];
            const float4* row = (const float4*)(x + (size_t)gw * HW);
            const float4* bbr = (const float4*)(g_bb + (size_t)b * HW);
            float s = 0.f, m = 0.f;
            #pragma unroll
            for (int i = 0; i < 24; i++) {
                float4 v = row[i * 32 + lane];
                float4 g = bbr[i * 32 + lane];
                float a = g.x * fmaxf(keep * v.x, 0.f);
                float e = g.y * fmaxf(keep * v.y, 0.f);
                float c = g.z * fmaxf(keep * v.z, 0.f);
                float d = g.w * fmaxf(keep * v.w, 0.f);
                s += (a + e) + (c + d);
                m = fmaxf(m, fmaxf(fmaxf(a, e), fmaxf(c, d)));
            }
            if (lane < 16) {
                float4 v = row[768 + lane];
                float4 g = bbr[768 + lane];
                float a = g.x * fmaxf(keep * v.x, 0.f);
                float e = g.y * fmaxf(keep * v.y, 0.f);
                float c = g.z * fmaxf(keep * v.z, 0.f);
                float d = g.w * fmaxf(keep * v.w, 0.f);
                s += (a + e) + (c + d);
                m = fmaxf(m, fmaxf(fmaxf(a, e), fmaxf(c, d)));
            }
            #pragma unroll
            for (int o = 16; o; o >>= 1)
                s += __shfl_down_sync(0xFFFFFFFFu, s, o);
            m = warp_max_nonneg(m);
            if (lane == 0) { g_xmax[gw] = m; g_psum[gw] = s; }
        }
    }
    grid_barrier();

    // ========================= PHASE K4 ===================================
    // FC gates. Logical grid: 256 units (b=bid>>3, c-eighth=bid&7); 8 warps,
    // each warp 8 outputs, lanes split over k (float4, coalesced).
    if (bid < 8 * BB) {
        float* pooled = sh;                       // [512]
        int b = bid >> 3, c8 = bid & 7;
        pooled[t]       = g_psum[b * CC + t]       * (1.0f / HW);
        pooled[t + 256] = g_psum[b * CC + t + 256] * (1.0f / HW);
        __syncthreads();
        const float4* pl4 = (const float4*)pooled;
        #pragma unroll
        for (int cc = 0; cc < 8; cc++) {
            int c = (c8 << 6) + (wid << 3) + cc;
            const float4* w1r = (const float4*)(W1 + (size_t)c * CC);
            const float4* w3r = (const float4*)(W3 + (size_t)c * CC);
            float d1 = 0.f, d3 = 0.f;
            #pragma unroll
            for (int j = 0; j < 4; j++) {
                int k = lane + (j << 5);
                float4 p = pl4[k];
                float4 a = w1r[k];
                float4 q = w3r[k];
                d1 = fmaf(a.x, p.x, fmaf(a.y, p.y, fmaf(a.z, p.z, fmaf(a.w, p.w, d1))));
                d3 = fmaf(q.x, p.x, fmaf(q.y, p.y, fmaf(q.z, p.z, fmaf(q.w, p.w, d3))));
            }
            #pragma unroll
            for (int o = 16; o; o >>= 1) {
                d1 += __shfl_down_sync(0xFFFFFFFFu, d1, o);
                d3 += __shfl_down_sync(0xFFFFFFFFu, d3, o);
            }
            if (lane == 0) {
                float c1 = 1.f / (1.f + expf(-d1));
                float r3 = fmaxf(d3, 0.f);
                float c3 = (r3 < 1.0f) ? 1.2f : r3;
                g_thres[b * CC + c] = c1 * c3 * g_xmax[b * CC + c];
            }
        }
    }
    grid_barrier();

    // ========================= PHASE K5 ===================================
    // final thresholding; grid-stride: 12845056 float4 / 131072 thr = 98 iters
    {
        const unsigned stride = NBLK * NTHR;              // 131072
        unsigned v0 = bid * NTHR + t;
        #pragma unroll 2
        for (unsigned i = 0; i < 98; i++) {
            unsigned e = (v0 + i * stride) * 4u;
            unsigned bc  = e / HW;
            unsigned pos = e % HW;
            unsigned b   = bc >> 9;
            float keep = g_keep[bc];
            float th   = g_thres[bc];
            float4 g  = *(const float4*)(g_bb + b * HW + pos);
            float4 xv = *(const float4*)(x + e);
            float4 o;
            float tt;
            tt = g.x * fmaxf(keep * xv.x, 0.f); o.x = (tt < th) ? 0.f : tt;
            tt = g.y * fmaxf(keep * xv.y, 0.f); o.y = (tt < th) ? 0.f : tt;
            tt = g.z * fmaxf(keep * xv.z, 0.f); o.z = (tt < th) ? 0.f : tt;
            tt = g.w * fmaxf(keep * xv.w, 0.f); o.w = (tt < th) ? 0.f : tt;
            *(float4*)(out + e) = o;
        }
    }
}

// ---------------------------------------------------------------------------
extern "C" void kernel_launch(void* const* d_in, const int* in_sizes, int n_in,
                              void* d_out, int out_size) {
    const float* x  = (const float*)d_in[0];
    const float* W1 = (const float*)d_in[1];
    const float* W3 = (const float*)d_in[2];
    float* out = (float*)d_out;
    pam_persistent<<<NBLK, NTHR>>>(x, W1, W3, out);
}

// round 17
// speedup vs baseline: 3.1504x; 1.0831x over previous
#include <cuda_runtime.h>
#include <cuda_bf16.h>

#define BB   32
#define CC   512
#define HW   3136            // 56*56
#define BC   (BB*CC)         // 16384
#define BHW  (BB*HW)         // 100352
#define CSPLIT 4
#define CGRP  (CC/CSPLIT)    // 128
#define CHUNK 1024
#define NCHUNK 4
#define NBLK 512
#define NTHR 256

__device__ float g_keep[BC];
__device__ float g_xmax[BC];
__device__ float g_psum[BC];
__device__ float g_thres[BC];
__device__ float g_bb[BHW];
__device__ float g_pmax[CSPLIT * BHW];
__device__ float g_pcsm[CSPLIT * BHW];
__device__ float g_spS[NCHUNK * BC];
__device__ float g_spM[NCHUNK * BC];
__device__ unsigned g_count;   // returns to 0 after each barrier
__device__ unsigned g_gen;     // monotonic generation (replay-safe)

// single-instruction warp max for NON-NEGATIVE floats (u32 redux, sm_80+)
__device__ __forceinline__ float warp_max_nonneg(float v) {
    unsigned r;
    asm("redux.sync.max.u32 %0, %1, 0xffffffff;" : "=r"(r) : "r"(__float_as_uint(v)));
    return __uint_as_float(r);
}

__device__ __forceinline__ unsigned ld_acquire(const unsigned* p) {
    unsigned v;
    asm volatile("ld.global.acquire.gpu.u32 %0, [%1];" : "=r"(v) : "l"(p));
    return v;
}

// Grid barrier: all NBLK blocks resident (launch_bounds(256,4): 4*148=592>=512).
// Poll with acquire LOADS (no atomic-ALU serialization at the LTS).
__device__ __forceinline__ void grid_barrier() {
    __syncthreads();
    __threadfence();
    if (threadIdx.x == 0) {
        unsigned my = ld_acquire(&g_gen);             // read gen BEFORE arriving
        if (atomicAdd(&g_count, 1u) == NBLK - 1) {
            atomicExch(&g_count, 0u);
            __threadfence();
            atomicAdd(&g_gen, 1u);                    // release
        } else {
            while (ld_acquire(&g_gen) == my) { }      // acquire spin
        }
    }
    __syncthreads();
}

// ===========================================================================
// Kernel 1 (persistent): phases A -> C -> K3 -> K4 with 3 grid barriers.
// ===========================================================================
__global__ void __launch_bounds__(NTHR, 4) pam_phase1(
    const float* __restrict__ x, const float* __restrict__ W1,
    const float* __restrict__ W3)
{
    __shared__ float sh[2048];     // 8KB, reused per phase
    __shared__ int   sdirty[CSPLIT];

    const int bid  = blockIdx.x;
    const int t    = threadIdx.x;
    const int wid  = t >> 5, lane = t & 31;

    // ========================= PHASE A ====================================
    {
        float (*swS)[CGRP] = (float(*)[CGRP])sh;           // [8][128]
        float (*swM)[CGRP] = (float(*)[CGRP])(sh + 1024);  // [8][128]
        int chunk = bid & 3, cs = (bid >> 2) & 3, b = bid >> 4;
        int c0 = cs * CGRP;
        int pos = chunk * CHUNK + t * 4;
        bool valid = pos < HW;
        const float* xb = x + ((size_t)b * CC + c0) * HW + pos;

        float4 mx = make_float4(0.f, 0.f, 0.f, 0.f);
        float4 sm = make_float4(0.f, 0.f, 0.f, 0.f);
        #pragma unroll 4
        for (int c = 0; c < CGRP; c++) {
            float4 v = make_float4(0.f, 0.f, 0.f, 0.f);
            if (valid) v = *(const float4*)(xb + (size_t)c * HW);
            v.x = fmaxf(v.x, 0.f); v.y = fmaxf(v.y, 0.f);
            v.z = fmaxf(v.z, 0.f); v.w = fmaxf(v.w, 0.f);
            mx.x = fmaxf(mx.x, v.x); mx.y = fmaxf(mx.y, v.y);
            mx.z = fmaxf(mx.z, v.z); mx.w = fmaxf(mx.w, v.w);
            sm.x += v.x; sm.y += v.y; sm.z += v.z; sm.w += v.w;
            float ts = (v.x + v.y) + (v.z + v.w);
            float tm = fmaxf(fmaxf(v.x, v.y), fmaxf(v.z, v.w));
            #pragma unroll
            for (int o = 16; o; o >>= 1)
                ts += __shfl_down_sync(0xFFFFFFFFu, ts, o);
            tm = warp_max_nonneg(tm);
            if (lane == 0) { swS[wid][c] = ts; swM[wid][c] = tm; }
        }
        if (valid) {
            size_t o = (size_t)cs * BHW + (size_t)b * HW + pos;
            *(float4*)(g_pmax + o) = mx;
            *(float4*)(g_pcsm + o) = sm;
        }
        __syncthreads();
        if (t < CGRP) {
            float S = 0.f, M = 0.f;
            #pragma unroll
            for (int w = 0; w < 8; w++) { S += swS[w][t]; M = fmaxf(M, swM[w][t]); }
            int idx = chunk * BC + b * CC + c0 + t;
            g_spS[idx] = S;
            g_spM[idx] = M;
        }
    }
    grid_barrier();

    // ========================= PHASE C ====================================
    if (bid < NCHUNK * BB) {
        float (*skeep)[CGRP] = (float(*)[CGRP])sh;         // [4][128]
        int chunk = bid & 3, b = bid >> 2;
        if (t < CSPLIT) sdirty[t] = 0;
        __syncthreads();
        #pragma unroll
        for (int cs = 0; cs < CSPLIT; cs++) {
            if (t < CGRP) {
                int bc = b * CC + cs * CGRP + t;
                float S = 0.f, M = 0.f;
                #pragma unroll
                for (int ch = 0; ch < NCHUNK; ch++) {
                    S += g_spS[ch * BC + bc];
                    M  = fmaxf(M, g_spM[ch * BC + bc]);
                }
                float kp = ((M - S * (1.0f / HW)) < 0.5f) ? 0.f : 1.f;
                skeep[cs][t] = kp;
                if (chunk == 0) g_keep[bc] = kp;
                if (kp == 0.f) atomicOr(&sdirty[cs], 1);
            }
        }
        __syncthreads();

        int pos = chunk * CHUNK + t * 4;
        bool valid = pos < HW;
        #pragma unroll
        for (int cs = 0; cs < CSPLIT; cs++) {
            if (sdirty[cs] && valid) {
                const float* xb = x + ((size_t)b * CC + cs * CGRP) * HW + pos;
                float4 mx = make_float4(0.f, 0.f, 0.f, 0.f);
                float4 sm = make_float4(0.f, 0.f, 0.f, 0.f);
                #pragma unroll 8
                for (int c = 0; c < CGRP; c++) {
                    float4 v = *(const float4*)(xb + (size_t)c * HW);
                    float k = skeep[cs][c];
                    v.x = fmaxf(k * v.x, 0.f); v.y = fmaxf(k * v.y, 0.f);
                    v.z = fmaxf(k * v.z, 0.f); v.w = fmaxf(k * v.w, 0.f);
                    mx.x = fmaxf(mx.x, v.x); mx.y = fmaxf(mx.y, v.y);
                    mx.z = fmaxf(mx.z, v.z); mx.w = fmaxf(mx.w, v.w);
                    sm.x += v.x; sm.y += v.y; sm.z += v.z; sm.w += v.w;
                }
                size_t o = (size_t)cs * BHW + (size_t)b * HW + pos;
                *(float4*)(g_pmax + o) = mx;   // same-thread readback below
                *(float4*)(g_pcsm + o) = sm;
            }
        }
        if (valid) {
            size_t base = (size_t)b * HW + pos;
            float4 mx = *(const float4*)(g_pmax + base);
            float4 sm = *(const float4*)(g_pcsm + base);
            #pragma unroll
            for (int cs = 1; cs < CSPLIT; cs++) {
                float4 m2 = *(const float4*)(g_pmax + (size_t)cs * BHW + base);
                float4 s2 = *(const float4*)(g_pcsm + (size_t)cs * BHW + base);
                mx.x = fmaxf(mx.x, m2.x); mx.y = fmaxf(mx.y, m2.y);
                mx.z = fmaxf(mx.z, m2.z); mx.w = fmaxf(mx.w, m2.w);
                sm.x += s2.x; sm.y += s2.y; sm.z += s2.z; sm.w += s2.w;
            }
            float4 bb;
            bb.x = 1.f - expf(-(mx.x - sm.x * (1.0f / CC)));
            bb.y = 1.f - expf(-(mx.y - sm.y * (1.0f / CC)));
            bb.z = 1.f - expf(-(mx.z - sm.z * (1.0f / CC)));
            bb.w = 1.f - expf(-(mx.w - sm.w * (1.0f / CC)));
            *(float4*)(g_bb + base) = bb;
        }
    }
    grid_barrier();

    // ========================= PHASE K3 ===================================
    // Real block covers 32 CONSECUTIVE bc (one 128B line of g_xmax/g_psum).
    {
        #pragma unroll
        for (int j = 0; j < 4; j++) {
            int gw = bid * 32 + j * 8 + wid;     // bc
            int b = gw >> 9;
            float keep = g_keep[gw];
            const float4* row = (const float4*)(x + (size_t)gw * HW);
            const float4* bbr = (const float4*)(g_bb + (size_t)b * HW);
            float s = 0.f, m = 0.f;
            #pragma unroll
            for (int i = 0; i < 24; i++) {
                float4 v = row[i * 32 + lane];
                float4 g = bbr[i * 32 + lane];
                float a = g.x * fmaxf(keep * v.x, 0.f);
                float e = g.y * fmaxf(keep * v.y, 0.f);
                float c = g.z * fmaxf(keep * v.z, 0.f);
                float d = g.w * fmaxf(keep * v.w, 0.f);
                s += (a + e) + (c + d);
                m = fmaxf(m, fmaxf(fmaxf(a, e), fmaxf(c, d)));
            }
            if (lane < 16) {
                float4 v = row[768 + lane];
                float4 g = bbr[768 + lane];
                float a = g.x * fmaxf(keep * v.x, 0.f);
                float e = g.y * fmaxf(keep * v.y, 0.f);
                float c = g.z * fmaxf(keep * v.z, 0.f);
                float d = g.w * fmaxf(keep * v.w, 0.f);
                s += (a + e) + (c + d);
                m = fmaxf(m, fmaxf(fmaxf(a, e), fmaxf(c, d)));
            }
            #pragma unroll
            for (int o = 16; o; o >>= 1)
                s += __shfl_down_sync(0xFFFFFFFFu, s, o);
            m = warp_max_nonneg(m);
            if (lane == 0) { g_xmax[gw] = m; g_psum[gw] = s; }
        }
    }
    grid_barrier();

    // ========================= PHASE K4 ===================================
    if (bid < 8 * BB) {
        float* pooled = sh;                       // [512]
        int b = bid >> 3, c8 = bid & 7;
        pooled[t]       = g_psum[b * CC + t]       * (1.0f / HW);
        pooled[t + 256] = g_psum[b * CC + t + 256] * (1.0f / HW);
        __syncthreads();
        const float4* pl4 = (const float4*)pooled;
        #pragma unroll
        for (int cc = 0; cc < 8; cc++) {
            int c = (c8 << 6) + (wid << 3) + cc;
            const float4* w1r = (const float4*)(W1 + (size_t)c * CC);
            const float4* w3r = (const float4*)(W3 + (size_t)c * CC);
            float d1 = 0.f, d3 = 0.f;
            #pragma unroll
            for (int j = 0; j < 4; j++) {
                int k = lane + (j << 5);
                float4 p = pl4[k];
                float4 a = w1r[k];
                float4 q = w3r[k];
                d1 = fmaf(a.x, p.x, fmaf(a.y, p.y, fmaf(a.z, p.z, fmaf(a.w, p.w, d1))));
                d3 = fmaf(q.x, p.x, fmaf(q.y, p.y, fmaf(q.z, p.z, fmaf(q.w, p.w, d3))));
            }
            #pragma unroll
            for (int o = 16; o; o >>= 1) {
                d1 += __shfl_down_sync(0xFFFFFFFFu, d1, o);
                d3 += __shfl_down_sync(0xFFFFFFFFu, d3, o);
            }
            if (lane == 0) {
                float c1 = 1.f / (1.f + expf(-d1));
                float r3 = fmaxf(d3, 0.f);
                float c3 = (r3 < 1.0f) ? 1.2f : r3;
                g_thres[b * CC + c] = c1 * c3 * g_xmax[b * CC + c];
            }
        }
    }
}

// ===========================================================================
// Kernel 2: final thresholding — standalone for full occupancy (regs ~22).
// ===========================================================================
__global__ void k5_final(const float* __restrict__ x, float* __restrict__ out) {
    unsigned v = blockIdx.x * blockDim.x + threadIdx.x;
    unsigned e = v * 4u;
    if (e >= (unsigned)BB * CC * HW) return;
    unsigned bc  = e / HW;
    unsigned pos = e % HW;
    unsigned b   = bc >> 9;
    float keep = g_keep[bc];
    float th   = g_thres[bc];
    float4 g  = *(const float4*)(g_bb + b * HW + pos);
    float4 xv = *(const float4*)(x + e);
    float4 o;
    float t;
    t = g.x * fmaxf(keep * xv.x, 0.f); o.x = (t < th) ? 0.f : t;
    t = g.y * fmaxf(keep * xv.y, 0.f); o.y = (t < th) ? 0.f : t;
    t = g.z * fmaxf(keep * xv.z, 0.f); o.z = (t < th) ? 0.f : t;
    t = g.w * fmaxf(keep * xv.w, 0.f); o.w = (t < th) ? 0.f : t;
    *(float4*)(out + e) = o;
}

// ---------------------------------------------------------------------------
extern "C" void kernel_launch(void* const* d_in, const int* in_sizes, int n_in,
                              void* d_out, int out_size) {
    const float* x  = (const float*)d_in[0];
    const float* W1 = (const float*)d_in[1];
    const float* W3 = (const float*)d_in[2];
    float* out = (float*)d_out;

    pam_phase1<<<NBLK, NTHR>>>(x, W1, W3);
    unsigned nvec = (unsigned)BB * CC * HW / 4u;
    k5_final<<<(nvec + 255) / 256, 256>>>(x, out);
}